// round 16
// baseline (speedup 1.0000x reference)
#include <cuda_runtime.h>
#include <cuda_bf16.h>
#include <math.h>
#include <stdint.h>

// Problem constants
#define N_CLASS 32000
#define EMB     256
#define HID     512
#define BATCH   256
#define SEQ     64
#define G4      2048            // 4 gates * HID (gate-interleaved: n = u*4 + g)
#define MB_     (SEQ*BATCH)     // 16384
#define BH      (BATCH*HID)     // 131072

typedef unsigned long long u64;
typedef unsigned short u16;

// ---------------- static device scratch (allocation-free) ----------------
__device__ __align__(16) float g_gin  [MB_*G4];         // 134 MB gate inputs
__device__ __align__(16) float g_wicat[G4*EMB];         // fp32 (fold + beff source)
__device__ __align__(16) float g_bcat [G4];
__device__ __align__(16) float g_weff [G4*HID];
__device__ __align__(16) float g_beff [G4];
__device__ __align__(16) u16   g_whqhi[G4*HID];         // hidden weights split bf16
__device__ __align__(16) u16   g_whqlo[G4*HID];
__device__ __align__(16) u16   g_hhi  [2*BH];           // h double buffer (split bf16)
__device__ __align__(16) u16   g_hlo  [2*BH];
__device__ unsigned          g_bcnt8[8];                // per-bm-group barrier counters
__device__ volatile unsigned g_bgen8[8];                // per-bm-group barrier generations
// split-bf16 operand buffers
__device__ __align__(16) u16 g_ahi[MB_*HID];            // emb, then h0all
__device__ __align__(16) u16 g_alo[MB_*HID];
__device__ __align__(16) u16 g_bhi[N_CLASS*HID];        // Wicat/Weff/Wfin split (B side)
__device__ __align__(16) u16 g_blo[N_CLASS*HID];
__device__ __align__(16) u16 g_w1hi[G4*EMB];            // Wicat split (from prep)
__device__ __align__(16) u16 g_w1lo[G4*EMB];
__device__ __align__(16) u16 g_w2hi[G4*HID];            // Weff split
__device__ __align__(16) u16 g_w2lo[G4*HID];

// ---------------- small helpers ----------------
__device__ __forceinline__ u64 pack2(float x, float y) {
    u64 r; asm("mov.b64 %0, {%1, %2};" : "=l"(r) : "f"(x), "f"(y)); return r;
}
__device__ __forceinline__ float2 unpack2(u64 v) {
    float2 r; asm("mov.b64 {%0, %1}, %2;" : "=f"(r.x), "=f"(r.y) : "l"(v)); return r;
}
__device__ __forceinline__ void fma2(u64& d, u64 a, u64 b) {
    asm("fma.rn.f32x2 %0, %1, %2, %0;" : "+l"(d) : "l"(a), "l"(b));
}
__device__ __forceinline__ float sigmoidf_(float x) { return 1.0f / (1.0f + expf(-x)); }
__device__ __forceinline__ uint32_t smem_u32(const void* p) {
    uint32_t a;
    asm("{ .reg .u64 t; cvta.to.shared.u64 t, %1; cvt.u32.u64 %0, t; }"
        : "=r"(a) : "l"(p));
    return a;
}
__device__ __forceinline__ void split_bf16(float x, u16& hi, u16& lo) {
    __nv_bfloat16 h = __float2bfloat16(x);
    hi = __bfloat16_as_ushort(h);
    lo = __bfloat16_as_ushort(__float2bfloat16(x - __bfloat162float(h)));
}
__device__ __forceinline__ void st_cg_u16(u16* p, u16 v) {
    asm volatile("st.global.cg.u16 [%0], %1;" :: "l"(p), "h"(v));
}

// ---------------- cp.async helpers ----------------
__device__ __forceinline__ void cp16(uint32_t saddr, const void* g) {
    asm volatile("cp.async.cg.shared.global [%0], [%1], 16;"
                 :: "r"(saddr), "l"(g) : "memory");
}
#define CP_COMMIT() asm volatile("cp.async.commit_group;" ::: "memory")
#define CP_WAIT2()  asm volatile("cp.async.wait_group 2;" ::: "memory")
#define CP_WAIT1()  asm volatile("cp.async.wait_group 1;" ::: "memory")
#define CP_WAIT0()  asm volatile("cp.async.wait_group 0;" ::: "memory")

// ---------------- mma.sync helpers (legacy tensor path, valid on sm_103) -----
__device__ __forceinline__ void ldm_x4(uint32_t* r, uint32_t addr) {
    asm volatile("ldmatrix.sync.aligned.m8n8.x4.shared.b16 {%0,%1,%2,%3}, [%4];"
                 : "=r"(r[0]), "=r"(r[1]), "=r"(r[2]), "=r"(r[3]) : "r"(addr));
}
__device__ __forceinline__ void mma16816(float* c, const uint32_t* a,
                                         uint32_t b0, uint32_t b1) {
    asm volatile(
        "mma.sync.aligned.m16n8k16.row.col.f32.bf16.bf16.f32 "
        "{%0,%1,%2,%3}, {%4,%5,%6,%7}, {%8,%9}, {%0,%1,%2,%3};"
        : "+f"(c[0]), "+f"(c[1]), "+f"(c[2]), "+f"(c[3])
        : "r"(a[0]), "r"(a[1]), "r"(a[2]), "r"(a[3]), "r"(b0), "r"(b1));
}

// ------------- build gate-interleaved weights (whq + wicat splits) -----------
__global__ void __launch_bounds__(256) prep_concat_kernel(
    const float* __restrict__ Wii, const float* __restrict__ Whi, const float* __restrict__ bi,
    const float* __restrict__ Wif, const float* __restrict__ Whf, const float* __restrict__ bf,
    const float* __restrict__ Wig, const float* __restrict__ Whg, const float* __restrict__ bg,
    const float* __restrict__ Wio, const float* __restrict__ Who, const float* __restrict__ bo)
{
    int idx = blockIdx.x * 256 + threadIdx.x;
    if (idx >= G4 * HID) return;
    int n = idx / HID;
    int k = idx - n * HID;
    int u = n >> 2;
    int g = n & 3;
    const float* Wh = (g == 0) ? Whi : (g == 1) ? Whf : (g == 2) ? Whg : Who;
    u16 hi, lo;
    split_bf16(Wh[u * HID + k], hi, lo);
    g_whqhi[idx] = hi;
    g_whqlo[idx] = lo;
    if (k < EMB) {
        const float* Wi = (g == 0) ? Wii : (g == 1) ? Wif : (g == 2) ? Wig : Wio;
        float v = Wi[u * EMB + k];
        g_wicat[n * EMB + k] = v;
        u16 h2, l2; split_bf16(v, h2, l2);
        g_w1hi[n * EMB + k] = h2;
        g_w1lo[n * EMB + k] = l2;
    }
    if (k == 0) {
        const float* bv = (g == 0) ? bi : (g == 1) ? bf : (g == 2) ? bg : bo;
        g_bcat[n] = bv[u];
    }
}

// ------------- embedding gather -> split bf16 directly -------------
__global__ void __launch_bounds__(EMB) embed_kernel(const int* __restrict__ X,
                                                    const float* __restrict__ C)
{
    int sb = blockIdx.x;
    int s  = sb >> 8;
    int b  = sb & 255;
    int row = X[b * SEQ + s];
    float v = C[(size_t)row * EMB + threadIdx.x];
    u16 hi, lo;
    split_bf16(v, hi, lo);
    g_ahi[(size_t)sb * EMB + threadIdx.x] = hi;
    g_alo[(size_t)sb * EMB + threadIdx.x] = lo;
}

// ------------- fp32 -> split bf16 (hi + lo) -------------
__global__ void __launch_bounds__(256) cvt_split_kernel(
    const float* __restrict__ src, u16* __restrict__ hi,
    u16* __restrict__ lo, int n)
{
    int i = blockIdx.x * 256 + threadIdx.x;
    if (i >= n) return;
    u16 h, l;
    split_bf16(src[i], h, l);
    hi[i] = h;
    lo[i] = l;
}

// ------------- split-bf16 tensor-core GEMM, 4-stage x 16k cp.async ------------
// Y[m][n] = bias[n] + sum_k A[m][k]*B[n][k]   (3-term compensated bf16)
// CTA tile 128x128, 8 warps (warp w: m-block (w&3)*32, n-block (w>>2)*64).
// Stage = 16 k; rows padded to 48 B (conflict-free ldmatrix: 8 addrs x 48B
// apart hit 8 distinct 16B phases). 4 stages x 24576 B = 98304 B -> 2 CTA/SM.
#define MG_ROWU  24
#define MG_ARRU  (128*MG_ROWU)            // 3072 u16 per array per stage
#define MG_STGU  (4*MG_ARRU)              // 12288 u16 per stage
#define MG_SMEM  (4*MG_STGU*2)            // 98304 bytes

__device__ __forceinline__ void mg_issue_stage(
    uint32_t sbase, const u16* __restrict__ Ahi, const u16* __restrict__ Alo,
    const u16* __restrict__ Bhi, const u16* __restrict__ Blo,
    int bm, int bn, int K, int k0, int tid)
{
    int row = tid >> 1, seg = (tid & 1) * 8;   // 128 rows x 2 segs
    size_t ga = (size_t)(bm + row) * K + k0 + seg;
    size_t gb = (size_t)(bn + row) * K + k0 + seg;
    uint32_t d = sbase + (uint32_t)((row * MG_ROWU + seg) * 2);
    cp16(d + 0u * (MG_ARRU * 2), Ahi + ga);
    cp16(d + 1u * (MG_ARRU * 2), Alo + ga);
    cp16(d + 2u * (MG_ARRU * 2), Bhi + gb);
    cp16(d + 3u * (MG_ARRU * 2), Blo + gb);
}

__global__ void __launch_bounds__(256, 2) mma_gemm_kernel(
    const u16* __restrict__ Ahi, const u16* __restrict__ Alo,
    const u16* __restrict__ Bhi, const u16* __restrict__ Blo,
    const float* __restrict__ bias, float* __restrict__ Y, int N, int K)
{
    extern __shared__ u16 smu[];
    uint32_t smb = smem_u32(smu);
    int tid  = threadIdx.x;
    int w    = tid >> 5;
    int lane = tid & 31;
    int bm = blockIdx.y * 128;
    int bn = blockIdx.x * 128;
    int wm = (w & 3) * 32;
    int wn = (w >> 2) * 64;
    int nch = K >> 4;                 // 16-k chunks

    int mat = lane >> 3, mi = lane & 7;
    // byte offsets within an array (row stride 48 B)
    uint32_t aoff = (uint32_t)((wm + (mat & 1) * 8 + mi) * 48 + (mat >> 1) * 16);
    uint32_t boff = (uint32_t)((wn + (mat >> 1) * 8 + mi) * 48 + (mat & 1) * 16);

    float acc[2][8][4];
#pragma unroll
    for (int i = 0; i < 2; i++)
#pragma unroll
        for (int j = 0; j < 8; j++)
#pragma unroll
            for (int q = 0; q < 4; q++) acc[i][j][q] = 0.0f;

    // prologue: stages 0..2
#pragma unroll
    for (int p = 0; p < 3; p++) {
        if (p < nch)
            mg_issue_stage(smb + (uint32_t)(p * MG_STGU * 2),
                           Ahi, Alo, Bhi, Blo, bm, bn, K, p * 16, tid);
        CP_COMMIT();
    }

    for (int c = 0; c < nch; c++) {
        CP_WAIT2();
        __syncthreads();
        if (c + 3 < nch)
            mg_issue_stage(smb + (uint32_t)(((c + 3) & 3) * MG_STGU * 2),
                           Ahi, Alo, Bhi, Blo, bm, bn, K, (c + 3) * 16, tid);
        CP_COMMIT();

        uint32_t sb = smb + (uint32_t)((c & 3) * MG_STGU * 2);
        uint32_t ah[2][4], al[2][4];
        ldm_x4(ah[0], sb + 0 * (MG_ARRU * 2) + aoff);
        ldm_x4(ah[1], sb + 0 * (MG_ARRU * 2) + aoff + 16 * 48);
        ldm_x4(al[0], sb + 1 * (MG_ARRU * 2) + aoff);
        ldm_x4(al[1], sb + 1 * (MG_ARRU * 2) + aoff + 16 * 48);
#pragma unroll
        for (int nb = 0; nb < 4; nb++) {
            uint32_t bh[4], bl[4];
            uint32_t bo = boff + (uint32_t)(nb * 16 * 48);
            ldm_x4(bh, sb + 2 * (MG_ARRU * 2) + bo);
            ldm_x4(bl, sb + 3 * (MG_ARRU * 2) + bo);
#pragma unroll
            for (int mb = 0; mb < 2; mb++) {
#pragma unroll
                for (int h = 0; h < 2; h++) {
                    float* cc = acc[mb][nb * 2 + h];
                    mma16816(cc, ah[mb], bh[2 * h], bh[2 * h + 1]);
                    mma16816(cc, ah[mb], bl[2 * h], bl[2 * h + 1]);
                    mma16816(cc, al[mb], bh[2 * h], bh[2 * h + 1]);
                }
            }
        }
    }

    int grp = lane >> 2, t2 = lane & 3;
#pragma unroll
    for (int mb = 0; mb < 2; mb++) {
#pragma unroll
        for (int nj = 0; nj < 8; nj++) {
            int n = bn + wn + nj * 8 + t2 * 2;
            float2 bv = *(const float2*)&bias[n];
            int mlo = bm + wm + mb * 16 + grp;
            const float* cc = acc[mb][nj];
            float2 v0 = make_float2(cc[0] + bv.x, cc[1] + bv.y);
            float2 v1 = make_float2(cc[2] + bv.x, cc[3] + bv.y);
            *(float2*)&Y[(size_t)mlo * N + n]       = v0;
            *(float2*)&Y[(size_t)(mlo + 8) * N + n] = v1;
        }
    }
}

// ------------- fp32 fold GEMM (known-good), TRANSB -------------
template <bool TRANSB>
__global__ void __launch_bounds__(256) gemm128_kernel(
    const float* __restrict__ A, const float* __restrict__ B,
    const float* __restrict__ bias, float* __restrict__ Y,
    int M, int N, int K)
{
    const int BK = 16;
    __shared__ float As[BK][128];
    __shared__ float Bs[BK][128];

    int bm = blockIdx.y * 128;
    int bn = blockIdx.x * 128;
    int tid = threadIdx.x;
    int tx = tid & 15;
    int ty = tid >> 4;
    int m0 = ty * 8;
    int n0 = tx * 8;

    u64 acc[8][4];
#pragma unroll
    for (int i = 0; i < 8; i++)
#pragma unroll
        for (int j = 0; j < 4; j++) acc[i][j] = 0ULL;

    for (int k0 = 0; k0 < K; k0 += BK) {
#pragma unroll
        for (int l = tid; l < 512; l += 256) {
            int r = l >> 2, kq = l & 3;
            float4 v = *(const float4*)&A[(size_t)(bm + r) * K + k0 + kq * 4];
            As[kq * 4 + 0][r] = v.x; As[kq * 4 + 1][r] = v.y;
            As[kq * 4 + 2][r] = v.z; As[kq * 4 + 3][r] = v.w;
        }
        if (!TRANSB) {
#pragma unroll
            for (int l = tid; l < 512; l += 256) {
                int r = l >> 2, kq = l & 3;
                float4 v = *(const float4*)&B[(size_t)(bn + r) * K + k0 + kq * 4];
                Bs[kq * 4 + 0][r] = v.x; Bs[kq * 4 + 1][r] = v.y;
                Bs[kq * 4 + 2][r] = v.z; Bs[kq * 4 + 3][r] = v.w;
            }
        } else {
#pragma unroll
            for (int l = tid; l < 512; l += 256) {
                int k = l >> 5, nq = l & 31;
                *(float4*)&Bs[k][nq * 4] =
                    *(const float4*)&B[(size_t)(k0 + k) * N + bn + nq * 4];
            }
        }
        __syncthreads();

#pragma unroll
        for (int k = 0; k < BK; k++) {
            float4 av0 = *(const float4*)&As[k][m0];
            float4 av1 = *(const float4*)&As[k][m0 + 4];
            u64 bp[4];
            bp[0] = *(const u64*)&Bs[k][n0];
            bp[1] = *(const u64*)&Bs[k][n0 + 2];
            bp[2] = *(const u64*)&Bs[k][n0 + 4];
            bp[3] = *(const u64*)&Bs[k][n0 + 6];
            float am[8] = {av0.x, av0.y, av0.z, av0.w, av1.x, av1.y, av1.z, av1.w};
#pragma unroll
            for (int i = 0; i < 8; i++) {
                u64 ad = pack2(am[i], am[i]);
#pragma unroll
                for (int j = 0; j < 4; j++) fma2(acc[i][j], ad, bp[j]);
            }
        }
        __syncthreads();
    }

#pragma unroll
    for (int i = 0; i < 8; i++) {
        int m = bm + m0 + i;
        float2 p0 = unpack2(acc[i][0]), p1 = unpack2(acc[i][1]);
        float2 p2 = unpack2(acc[i][2]), p3 = unpack2(acc[i][3]);
        float4 v0 = make_float4(p0.x, p0.y, p1.x, p1.y);
        float4 v1 = make_float4(p2.x, p2.y, p3.x, p3.y);
        *(float4*)&Y[(size_t)m * N + bn + n0]     = v0;
        *(float4*)&Y[(size_t)m * N + bn + n0 + 4] = v1;
    }
}

// ------------- per-bm-group barrier (16 blocks each, all co-resident) ---------
__device__ __forceinline__ void groupbar(int gid, unsigned target)
{
    __threadfence();
    __syncthreads();
    if (threadIdx.x == 0) {
        if (atomicAdd(&g_bcnt8[gid], 1u) == 15u) {
            g_bcnt8[gid] = 0u;
            __threadfence();
            g_bgen8[gid] = target;
        } else {
            while (g_bgen8[gid] < target) { }
        }
    }
    __syncthreads();
}

// ------------- persistent LSTM layer: 512 threads, resident-B + 3-slot ring ---
// Step 0 skips the GEMM entirely (h_prev == 0 -> gates = gin exactly).
#define LSR_A_LO  16640
#define LSR_RES   33280
#define LSR_RING  (33280 + 5*10240)          // 84480
#define LSR_SMEMU (84480 + 3*10240)          // 115200 u16
#define LSR_SMEM  (LSR_SMEMU*2)              // 230400 bytes

__device__ __forceinline__ void lsr_issue_chunk(uint32_t smb, uint32_t off_u16,
                                                int bn, int k0, int tid)
{
    int r = tid >> 2, seg = (tid & 3) * 8;
    size_t g = (size_t)(bn + r) * HID + k0 + seg;
    uint32_t d = smb + (off_u16 + (uint32_t)(r * 40 + seg)) * 2;
    cp16(d, g_whqhi + g);
    cp16(d + 5120 * 2, g_whqlo + g);
}

__global__ void __launch_bounds__(512) lstm_layer_mma_kernel(int store_all)
{
    extern __shared__ u16 smu[];
    uint32_t smb = smem_u32(smu);
    int tid  = threadIdx.x;
    int w    = tid >> 5;
    int lane = tid & 31;
    int bn = blockIdx.x * 128;
    int bm = blockIdx.y * 32;
    int gid = blockIdx.y;
    int wm = (w & 1) * 16;
    int wn = (w >> 1) * 16;            // 8 n-slices of 16 gates

    int mat = lane >> 3, mi = lane & 7;
    uint32_t aoff = (uint32_t)((wm + (mat & 1) * 8 + mi) * 1040 + (mat >> 1) * 16);
    uint32_t boff = (uint32_t)((wn + (mat >> 1) * 8 + mi) * 80 + (mat & 1) * 16);

    int grp = lane >> 2, t2 = lane & 3;
    int m0r = bm + wm + grp;
    bool owner = (t2 & 1) == 0;

    float cst[2][2];
#pragma unroll
    for (int j = 0; j < 2; j++) { cst[j][0] = 0.0f; cst[j][1] = 0.0f; }

    // prologue: resident chunks 0..4 (one group), then ring chunks 5,6
    for (int c = 0; c < 5; c++)
        lsr_issue_chunk(smb, (uint32_t)(LSR_RES + c * 10240), bn, c * 32, tid);
    CP_COMMIT();
    lsr_issue_chunk(smb, (uint32_t)(LSR_RING + 0 * 10240), bn, 5 * 32, tid);
    CP_COMMIT();
    lsr_issue_chunk(smb, (uint32_t)(LSR_RING + 1 * 10240), bn, 6 * 32, tid);
    CP_COMMIT();

    for (int s = 0; s < SEQ; s++) {
        const u16* hp_hi = g_hhi + (s & 1) * BH;
        const u16* hp_lo = g_hlo + (s & 1) * BH;
        u16* hn_hi = g_hhi + ((s + 1) & 1) * BH;
        u16* hn_lo = g_hlo + ((s + 1) & 1) * BH;

        // prefetch this step's gin into registers (no h dependency)
        float2 pg0[2], pg1[2];
#pragma unroll
        for (int nj = 0; nj < 2; nj++) {
            int ncol = bn + wn + nj * 8 + t2 * 2;
            const float* gp = &g_gin[((size_t)(s * BATCH + m0r)) * G4 + ncol];
            pg0[nj] = *(const float2*)gp;
            pg1[nj] = *(const float2*)(gp + 8 * G4);
        }

        float acc[2][4];
#pragma unroll
        for (int j = 0; j < 2; j++)
#pragma unroll
            for (int q = 0; q < 4; q++) acc[j][q] = 0.0f;

        if (s > 0) {
            // group barrier: previous step's h stores must be visible
            groupbar(gid, (unsigned)s);

            // A load (h prev, 32 rows x 512 u16, hi+lo) -- 512 threads
#pragma unroll
            for (int t = 0; t < 4; t++) {
                int i = tid + t * 512;          // 0..2047
                int r = i >> 6, cseg = (i & 63) * 8;
                size_t g = (size_t)(bm + r) * HID + cseg;
                cp16(smb + (uint32_t)((r * 520 + cseg) * 2), hp_hi + g);
                cp16(smb + (uint32_t)((LSR_A_LO + r * 520 + cseg) * 2), hp_lo + g);
            }
            CP_COMMIT();

            // chunk 0 gate: A (+ anything earlier) fully arrived
            CP_WAIT0();
            __syncthreads();

            for (int ch = 0; ch < 16; ch++) {
                uint32_t bchunk;
                if (ch < 5) {
                    bchunk = (uint32_t)(LSR_RES + ch * 10240);
                } else {
                    if (ch > 5) {                 // ch==5 already covered by wait0
                        CP_WAIT1();
                        __syncthreads();
                    }
                    if (ch + 2 <= 15) {
                        int j = ch + 2;
                        lsr_issue_chunk(smb, (uint32_t)(LSR_RING + ((j - 5) % 3) * 10240),
                                        bn, j * 32, tid);
                        CP_COMMIT();
                    }
                    bchunk = (uint32_t)(LSR_RING + ((ch - 5) % 3) * 10240);
                }

                uint32_t bbase = smb + bchunk * 2 + boff;
#pragma unroll
                for (int k16 = 0; k16 < 2; k16++) {
                    uint32_t ka = (uint32_t)(ch * 64 + k16 * 32);
                    uint32_t kb = (uint32_t)(k16 * 32);
                    uint32_t ah[4], al[4], bh[4], bl[4];
                    ldm_x4(ah, smb + aoff + ka);
                    ldm_x4(al, smb + (uint32_t)(LSR_A_LO * 2) + aoff + ka);
                    ldm_x4(bh, bbase + kb);
                    ldm_x4(bl, bbase + (uint32_t)(5120 * 2) + kb);

                    mma16816(acc[0], ah, bh[0], bh[1]);
                    mma16816(acc[0], ah, bl[0], bl[1]);
                    mma16816(acc[0], al, bh[0], bh[1]);
                    mma16816(acc[1], ah, bh[2], bh[3]);
                    mma16816(acc[1], ah, bl[2], bl[3]);
                    mma16816(acc[1], al, bh[2], bh[3]);
                }
            }

            // all ring reads done before next step reuses slots 0/1
            __syncthreads();
        }

        if (s + 1 < SEQ) {
            lsr_issue_chunk(smb, (uint32_t)(LSR_RING + 0 * 10240), bn, 5 * 32, tid);
            CP_COMMIT();
            lsr_issue_chunk(smb, (uint32_t)(LSR_RING + 1 * 10240), bn, 6 * 32, tid);
            CP_COMMIT();
        }

        // epilogue: prefetched gin, gate pair-exchange, LSTM cell, h store
#pragma unroll
        for (int nj = 0; nj < 2; nj++) {
            int ncol = bn + wn + nj * 8 + t2 * 2;
            float fa = acc[nj][0] + pg0[nj].x;
            float fb = acc[nj][1] + pg0[nj].y;
            float fc = acc[nj][2] + pg1[nj].x;
            float fd = acc[nj][3] + pg1[nj].y;
            float pa = __shfl_xor_sync(0xffffffffu, fa, 1);
            float pb = __shfl_xor_sync(0xffffffffu, fb, 1);
            float pc = __shfl_xor_sync(0xffffffffu, fc, 1);
            float pd = __shfl_xor_sync(0xffffffffu, fd, 1);
            if (owner) {
                int u = ncol >> 2;
                {
                    float ig = sigmoidf_(fa), fg = sigmoidf_(fb);
                    float gg = tanhf(pa),     og = sigmoidf_(pb);
                    float cn = fg * cst[nj][0] + ig * gg;
                    cst[nj][0] = cn;
                    float hv = og * tanhf(cn);
                    u16 hi, lo; split_bf16(hv, hi, lo);
                    size_t idx = (size_t)m0r * HID + u;
                    st_cg_u16(&hn_hi[idx], hi);
                    st_cg_u16(&hn_lo[idx], lo);
                    if (store_all) {
                        size_t oidx = ((size_t)(s * BATCH + m0r)) * HID + u;
                        g_ahi[oidx] = hi; g_alo[oidx] = lo;
                    }
                }
                {
                    float ig = sigmoidf_(fc), fg = sigmoidf_(fd);
                    float gg = tanhf(pc),     og = sigmoidf_(pd);
                    float cn = fg * cst[nj][1] + ig * gg;
                    cst[nj][1] = cn;
                    float hv = og * tanhf(cn);
                    u16 hi, lo; split_bf16(hv, hi, lo);
                    size_t idx = (size_t)(m0r + 8) * HID + u;
                    st_cg_u16(&hn_hi[idx], hi);
                    st_cg_u16(&hn_lo[idx], lo);
                    if (store_all) {
                        size_t oidx = ((size_t)(s * BATCH + m0r + 8)) * HID + u;
                        g_ahi[oidx] = hi; g_alo[oidx] = lo;
                    }
                }
            }
        }
    }
}

// ------------- beff[n] = bcat[n] + sum_e Wicat[n][e] * b_proj[e] -------------
__global__ void __launch_bounds__(256) beff_kernel(const float* __restrict__ bproj)
{
    int n = blockIdx.x * 256 + threadIdx.x;
    if (n >= G4) return;
    float s = g_bcat[n];
    const float* w = &g_wicat[n * EMB];
    for (int e = 0; e < EMB; e++) s += w[e] * bproj[e];
    g_beff[n] = s;
}

// ------------- reset group barriers (h zeroing no longer needed) -------------
__global__ void reset_bar_kernel()
{
    int i = threadIdx.x;
    if (i < 8) { g_bcnt8[i] = 0u; g_bgen8[i] = 0u; }
}

// =============================== launch ===============================
extern "C" void kernel_launch(void* const* d_in, const int* in_sizes, int n_in,
                              void* d_out, int out_size)
{
    const int*   X    = (const int*)  d_in[0];
    const float* C    = (const float*)d_in[1];
    const float* Wii  = (const float*)d_in[2];
    const float* Whi  = (const float*)d_in[3];
    const float* bi   = (const float*)d_in[4];
    const float* Wif  = (const float*)d_in[5];
    const float* Whf  = (const float*)d_in[6];
    const float* bf   = (const float*)d_in[7];
    const float* Wig  = (const float*)d_in[8];
    const float* Whg  = (const float*)d_in[9];
    const float* bg   = (const float*)d_in[10];
    const float* Wio  = (const float*)d_in[11];
    const float* Who  = (const float*)d_in[12];
    const float* bo   = (const float*)d_in[13];
    const float* Wp   = (const float*)d_in[14];   // [EMB, HID]
    const float* bp   = (const float*)d_in[15];   // [EMB]
    const float* Wfin = (const float*)d_in[16];   // [N_CLASS, HID]
    const float* bfin = (const float*)d_in[17];   // [N_CLASS]
    float* out = (float*)d_out;

    float *p_gin, *p_wicat, *p_bcat, *p_weff, *p_beff;
    u16 *p_ahi, *p_alo, *p_bhi, *p_blo, *p_hhi, *p_hlo;
    u16 *p_w1hi, *p_w1lo, *p_w2hi, *p_w2lo;
    cudaGetSymbolAddress((void**)&p_gin,   g_gin);
    cudaGetSymbolAddress((void**)&p_wicat, g_wicat);
    cudaGetSymbolAddress((void**)&p_bcat,  g_bcat);
    cudaGetSymbolAddress((void**)&p_weff,  g_weff);
    cudaGetSymbolAddress((void**)&p_beff,  g_beff);
    cudaGetSymbolAddress((void**)&p_ahi,   g_ahi);
    cudaGetSymbolAddress((void**)&p_alo,   g_alo);
    cudaGetSymbolAddress((void**)&p_bhi,   g_bhi);
    cudaGetSymbolAddress((void**)&p_blo,   g_blo);
    cudaGetSymbolAddress((void**)&p_hhi,   g_hhi);
    cudaGetSymbolAddress((void**)&p_hlo,   g_hlo);
    cudaGetSymbolAddress((void**)&p_w1hi,  g_w1hi);
    cudaGetSymbolAddress((void**)&p_w1lo,  g_w1lo);
    cudaGetSymbolAddress((void**)&p_w2hi,  g_w2hi);
    cudaGetSymbolAddress((void**)&p_w2lo,  g_w2lo);

    cudaFuncSetAttribute(mma_gemm_kernel,
                         cudaFuncAttributeMaxDynamicSharedMemorySize, MG_SMEM);
    cudaFuncSetAttribute(lstm_layer_mma_kernel,
                         cudaFuncAttributeMaxDynamicSharedMemorySize, LSR_SMEM);

    // 1) weight prep (whq split, wicat fp32 + split)
    prep_concat_kernel<<<(G4 * HID) / 256, 256>>>(Wii, Whi, bi, Wif, Whf, bf,
                                                  Wig, Whg, bg, Wio, Who, bo);
    // 2) embedding gather -> split bf16 A
    embed_kernel<<<MB_, EMB>>>(X, C);

    // 3) Gin0 = Emb @ Wicat^T + bcat   [16384 x 2048], K=256
    mma_gemm_kernel<<<dim3(G4 / 128, MB_ / 128), 256, MG_SMEM>>>(
        p_ahi, p_alo, p_w1hi, p_w1lo, p_bcat, p_gin, G4, EMB);

    // 4) fold projection: Weff = Wicat @ Wp (fp32), beff; cvt to split bf16
    gemm128_kernel<true><<<dim3(HID / 128, G4 / 128), 256>>>(
        p_wicat, Wp, nullptr, p_weff, G4, HID, EMB);
    beff_kernel<<<G4 / 256, 256>>>(bp);
    cvt_split_kernel<<<(G4 * HID) / 256, 256>>>(p_weff, p_w2hi, p_w2lo, G4 * HID);

    // 5) layer-0 recurrence (persistent; s=0 GEMM skipped; h0all -> g_ahi/alo)
    reset_bar_kernel<<<1, 32>>>();
    lstm_layer_mma_kernel<<<dim3(16, 8), 512, LSR_SMEM>>>(1);

    // 6) Gin1 = H0all @ Weff^T + beff  [16384 x 2048], K=512
    mma_gemm_kernel<<<dim3(G4 / 128, MB_ / 128), 256, MG_SMEM>>>(
        p_ahi, p_alo, p_w2hi, p_w2lo, p_beff, p_gin, G4, HID);

    // 7) layer-1 recurrence
    reset_bar_kernel<<<1, 32>>>();
    lstm_layer_mma_kernel<<<dim3(16, 8), 512, LSR_SMEM>>>(0);

    // 8) logits = h_last @ Wfin^T + bfin  [256 x 32000], K=512
    //    (SEQ even -> final h in buffer 0 of g_hhi/g_hlo)
    cvt_split_kernel<<<(N_CLASS * HID) / 256, 256>>>(Wfin, p_bhi, p_blo, N_CLASS * HID);
    mma_gemm_kernel<<<dim3(N_CLASS / 128, BATCH / 128), 256, MG_SMEM>>>(
        p_hhi, p_hlo, p_bhi, p_blo, bfin, out, N_CLASS, HID);
}

// round 17
// speedup vs baseline: 1.0384x; 1.0384x over previous
#include <cuda_runtime.h>
#include <cuda_bf16.h>
#include <math.h>
#include <stdint.h>

// Problem constants
#define N_CLASS 32000
#define EMB     256
#define HID     512
#define BATCH   256
#define SEQ     64
#define G4      2048            // 4 gates * HID (gate-interleaved: n = u*4 + g)
#define MB_     (SEQ*BATCH)     // 16384
#define BH      (BATCH*HID)     // 131072

typedef unsigned long long u64;
typedef unsigned short u16;

// ---------------- static device scratch (allocation-free) ----------------
__device__ __align__(16) float g_gin  [MB_*G4];         // 134 MB gate inputs
__device__ __align__(16) float g_wicat[G4*EMB];         // fp32 (fold + beff source)
__device__ __align__(16) float g_bcat [G4];
__device__ __align__(16) float g_weff [G4*HID];
__device__ __align__(16) float g_beff [G4];
__device__ __align__(16) u16   g_whqhi[G4*HID];         // hidden weights split bf16
__device__ __align__(16) u16   g_whqlo[G4*HID];
__device__ __align__(16) u16   g_hhi  [2*BH];           // h double buffer (split bf16)
__device__ __align__(16) u16   g_hlo  [2*BH];
__device__ unsigned          g_bcnt8[8];                // per-bm-group barrier counters
__device__ volatile unsigned g_bgen8[8];                // per-bm-group barrier generations
// split-bf16 operand buffers
__device__ __align__(16) u16 g_ahi[MB_*HID];            // emb, then h0all
__device__ __align__(16) u16 g_alo[MB_*HID];
__device__ __align__(16) u16 g_bhi[N_CLASS*HID];        // Wfin split
__device__ __align__(16) u16 g_blo[N_CLASS*HID];
__device__ __align__(16) u16 g_w1hi[G4*EMB];            // Wicat split (from prep)
__device__ __align__(16) u16 g_w1lo[G4*EMB];
__device__ __align__(16) u16 g_w2hi[G4*HID];            // Weff split
__device__ __align__(16) u16 g_w2lo[G4*HID];

// ---------------- small helpers ----------------
__device__ __forceinline__ u64 pack2(float x, float y) {
    u64 r; asm("mov.b64 %0, {%1, %2};" : "=l"(r) : "f"(x), "f"(y)); return r;
}
__device__ __forceinline__ float2 unpack2(u64 v) {
    float2 r; asm("mov.b64 {%0, %1}, %2;" : "=f"(r.x), "=f"(r.y) : "l"(v)); return r;
}
__device__ __forceinline__ void fma2(u64& d, u64 a, u64 b) {
    asm("fma.rn.f32x2 %0, %1, %2, %0;" : "+l"(d) : "l"(a), "l"(b));
}
__device__ __forceinline__ float sigmoidf_(float x) { return 1.0f / (1.0f + expf(-x)); }
__device__ __forceinline__ uint32_t smem_u32(const void* p) {
    uint32_t a;
    asm("{ .reg .u64 t; cvta.to.shared.u64 t, %1; cvt.u32.u64 %0, t; }"
        : "=r"(a) : "l"(p));
    return a;
}
__device__ __forceinline__ void split_bf16(float x, u16& hi, u16& lo) {
    __nv_bfloat16 h = __float2bfloat16(x);
    hi = __bfloat16_as_ushort(h);
    lo = __bfloat16_as_ushort(__float2bfloat16(x - __bfloat162float(h)));
}
__device__ __forceinline__ void st_cg_u16(u16* p, u16 v) {
    asm volatile("st.global.cg.u16 [%0], %1;" :: "l"(p), "h"(v));
}

// ---------------- cp.async helpers ----------------
__device__ __forceinline__ void cp16(uint32_t saddr, const void* g) {
    asm volatile("cp.async.cg.shared.global [%0], [%1], 16;"
                 :: "r"(saddr), "l"(g) : "memory");
}
#define CP_COMMIT() asm volatile("cp.async.commit_group;" ::: "memory")
#define CP_WAIT1()  asm volatile("cp.async.wait_group 1;" ::: "memory")
#define CP_WAIT0()  asm volatile("cp.async.wait_group 0;" ::: "memory")

// ---------------- mma.sync helpers (legacy tensor path, valid on sm_103) -----
__device__ __forceinline__ void ldm_x4(uint32_t* r, uint32_t addr) {
    asm volatile("ldmatrix.sync.aligned.m8n8.x4.shared.b16 {%0,%1,%2,%3}, [%4];"
                 : "=r"(r[0]), "=r"(r[1]), "=r"(r[2]), "=r"(r[3]) : "r"(addr));
}
__device__ __forceinline__ void mma16816(float* c, const uint32_t* a,
                                         uint32_t b0, uint32_t b1) {
    asm volatile(
        "mma.sync.aligned.m16n8k16.row.col.f32.bf16.bf16.f32 "
        "{%0,%1,%2,%3}, {%4,%5,%6,%7}, {%8,%9}, {%0,%1,%2,%3};"
        : "+f"(c[0]), "+f"(c[1]), "+f"(c[2]), "+f"(c[3])
        : "r"(a[0]), "r"(a[1]), "r"(a[2]), "r"(a[3]), "r"(b0), "r"(b1));
}

// ------------- build gate-interleaved weights (whq + wicat splits) -----------
__global__ void __launch_bounds__(256) prep_concat_kernel(
    const float* __restrict__ Wii, const float* __restrict__ Whi, const float* __restrict__ bi,
    const float* __restrict__ Wif, const float* __restrict__ Whf, const float* __restrict__ bf,
    const float* __restrict__ Wig, const float* __restrict__ Whg, const float* __restrict__ bg,
    const float* __restrict__ Wio, const float* __restrict__ Who, const float* __restrict__ bo)
{
    int idx = blockIdx.x * 256 + threadIdx.x;
    if (idx >= G4 * HID) return;
    int n = idx / HID;
    int k = idx - n * HID;
    int u = n >> 2;
    int g = n & 3;
    const float* Wh = (g == 0) ? Whi : (g == 1) ? Whf : (g == 2) ? Whg : Who;
    u16 hi, lo;
    split_bf16(Wh[u * HID + k], hi, lo);
    g_whqhi[idx] = hi;
    g_whqlo[idx] = lo;
    if (k < EMB) {
        const float* Wi = (g == 0) ? Wii : (g == 1) ? Wif : (g == 2) ? Wig : Wio;
        float v = Wi[u * EMB + k];
        g_wicat[n * EMB + k] = v;
        u16 h2, l2; split_bf16(v, h2, l2);
        g_w1hi[n * EMB + k] = h2;
        g_w1lo[n * EMB + k] = l2;
    }
    if (k == 0) {
        const float* bv = (g == 0) ? bi : (g == 1) ? bf : (g == 2) ? bg : bo;
        g_bcat[n] = bv[u];
    }
}

// ------------- embedding gather -> split bf16 directly -------------
__global__ void __launch_bounds__(EMB) embed_kernel(const int* __restrict__ X,
                                                    const float* __restrict__ C)
{
    int sb = blockIdx.x;
    int s  = sb >> 8;
    int b  = sb & 255;
    int row = X[b * SEQ + s];
    float v = C[(size_t)row * EMB + threadIdx.x];
    u16 hi, lo;
    split_bf16(v, hi, lo);
    g_ahi[(size_t)sb * EMB + threadIdx.x] = hi;
    g_alo[(size_t)sb * EMB + threadIdx.x] = lo;
}

// ------------- fp32 -> split bf16, vectorized 4 elems/thread -------------
// Requires n % 4 == 0 (true for all call sites).
__global__ void __launch_bounds__(256) cvt_split4_kernel(
    const float* __restrict__ src, u16* __restrict__ hi,
    u16* __restrict__ lo, int n4)
{
    int i = blockIdx.x * 256 + threadIdx.x;
    if (i >= n4) return;
    float4 v = *(const float4*)(src + (size_t)i * 4);
    u16 h[4], l[4];
    split_bf16(v.x, h[0], l[0]);
    split_bf16(v.y, h[1], l[1]);
    split_bf16(v.z, h[2], l[2]);
    split_bf16(v.w, h[3], l[3]);
    *(u64*)(hi + (size_t)i * 4) = *(const u64*)h;
    *(u64*)(lo + (size_t)i * 4) = *(const u64*)l;
}

// ------------- split-bf16 tensor-core GEMM, 2-stage x 32k cp.async ------------
// (R12/R14 known-good form: measured 153 us on the Gin GEMM)
#define MG_ROWU  40
#define MG_ARRU  (128*MG_ROWU)            // 5120 u16 per array per stage
#define MG_STGU  (4*MG_ARRU)              // 20480 u16 per stage
#define MG_SMEM  (2*MG_STGU*2)            // 81920 bytes -> 2 CTAs/SM

__device__ __forceinline__ void mg_issue_stage(
    uint32_t sbase, const u16* __restrict__ Ahi, const u16* __restrict__ Alo,
    const u16* __restrict__ Bhi, const u16* __restrict__ Blo,
    int bm, int bn, int K, int k0, int tid)
{
#pragma unroll
    for (int t = 0; t < 2; t++) {
        int idx = tid + 256 * t;            // 0..511
        int row = idx >> 2, seg = (idx & 3) * 8;
        size_t ga = (size_t)(bm + row) * K + k0 + seg;
        size_t gb = (size_t)(bn + row) * K + k0 + seg;
        uint32_t d = sbase + (uint32_t)((row * MG_ROWU + seg) * 2);
        cp16(d + 0u * (MG_ARRU * 2), Ahi + ga);
        cp16(d + 1u * (MG_ARRU * 2), Alo + ga);
        cp16(d + 2u * (MG_ARRU * 2), Bhi + gb);
        cp16(d + 3u * (MG_ARRU * 2), Blo + gb);
    }
}

__global__ void __launch_bounds__(256, 2) mma_gemm_kernel(
    const u16* __restrict__ Ahi, const u16* __restrict__ Alo,
    const u16* __restrict__ Bhi, const u16* __restrict__ Blo,
    const float* __restrict__ bias, float* __restrict__ Y, int N, int K)
{
    extern __shared__ u16 smu[];
    uint32_t smb = smem_u32(smu);
    int tid  = threadIdx.x;
    int w    = tid >> 5;
    int lane = tid & 31;
    int bm = blockIdx.y * 128;
    int bn = blockIdx.x * 128;
    int wm = (w & 3) * 32;
    int wn = (w >> 2) * 64;
    int nch = K >> 5;

    int mat = lane >> 3, mi = lane & 7;
    uint32_t aoff = (uint32_t)((wm + (mat & 1) * 8 + mi) * 80 + (mat >> 1) * 16);
    uint32_t boff = (uint32_t)((wn + (mat >> 1) * 8 + mi) * 80 + (mat & 1) * 16);

    float acc[2][8][4];
#pragma unroll
    for (int i = 0; i < 2; i++)
#pragma unroll
        for (int j = 0; j < 8; j++)
#pragma unroll
            for (int q = 0; q < 4; q++) acc[i][j][q] = 0.0f;

    mg_issue_stage(smb, Ahi, Alo, Bhi, Blo, bm, bn, K, 0, tid);
    CP_COMMIT();

    for (int c = 0; c < nch; c++) {
        CP_WAIT0();
        __syncthreads();
        if (c + 1 < nch)
            mg_issue_stage(smb + (uint32_t)(((c + 1) & 1) * MG_STGU * 2),
                           Ahi, Alo, Bhi, Blo, bm, bn, K, (c + 1) * 32, tid);
        CP_COMMIT();

        uint32_t sb = smb + (uint32_t)((c & 1) * MG_STGU * 2);
#pragma unroll
        for (int k16 = 0; k16 < 2; k16++) {
            uint32_t kb = (uint32_t)(k16 * 32);
            uint32_t ah[2][4], al[2][4];
            ldm_x4(ah[0], sb + 0 * 10240 + aoff + kb);
            ldm_x4(ah[1], sb + 0 * 10240 + aoff + kb + 16 * 80);
            ldm_x4(al[0], sb + 1 * 10240 + aoff + kb);
            ldm_x4(al[1], sb + 1 * 10240 + aoff + kb + 16 * 80);
#pragma unroll
            for (int nb = 0; nb < 4; nb++) {
                uint32_t bh[4], bl[4];
                uint32_t bo = boff + kb + (uint32_t)(nb * 16 * 80);
                ldm_x4(bh, sb + 2 * 10240 + bo);
                ldm_x4(bl, sb + 3 * 10240 + bo);
#pragma unroll
                for (int mb = 0; mb < 2; mb++) {
#pragma unroll
                    for (int h = 0; h < 2; h++) {
                        float* cc = acc[mb][nb * 2 + h];
                        mma16816(cc, ah[mb], bh[2 * h], bh[2 * h + 1]);
                        mma16816(cc, ah[mb], bl[2 * h], bl[2 * h + 1]);
                        mma16816(cc, al[mb], bh[2 * h], bh[2 * h + 1]);
                    }
                }
            }
        }
    }

    int grp = lane >> 2, t2 = lane & 3;
#pragma unroll
    for (int mb = 0; mb < 2; mb++) {
#pragma unroll
        for (int nj = 0; nj < 8; nj++) {
            int n = bn + wn + nj * 8 + t2 * 2;
            float2 bv = *(const float2*)&bias[n];
            int mlo = bm + wm + mb * 16 + grp;
            const float* cc = acc[mb][nj];
            float2 v0 = make_float2(cc[0] + bv.x, cc[1] + bv.y);
            float2 v1 = make_float2(cc[2] + bv.x, cc[3] + bv.y);
            *(float2*)&Y[(size_t)mlo * N + n]       = v0;
            *(float2*)&Y[(size_t)(mlo + 8) * N + n] = v1;
        }
    }
}

// ------------- fp32 fold GEMM (known-good), TRANSB -------------
template <bool TRANSB>
__global__ void __launch_bounds__(256) gemm128_kernel(
    const float* __restrict__ A, const float* __restrict__ B,
    const float* __restrict__ bias, float* __restrict__ Y,
    int M, int N, int K)
{
    const int BK = 16;
    __shared__ float As[BK][128];
    __shared__ float Bs[BK][128];

    int bm = blockIdx.y * 128;
    int bn = blockIdx.x * 128;
    int tid = threadIdx.x;
    int tx = tid & 15;
    int ty = tid >> 4;
    int m0 = ty * 8;
    int n0 = tx * 8;

    u64 acc[8][4];
#pragma unroll
    for (int i = 0; i < 8; i++)
#pragma unroll
        for (int j = 0; j < 4; j++) acc[i][j] = 0ULL;

    for (int k0 = 0; k0 < K; k0 += BK) {
#pragma unroll
        for (int l = tid; l < 512; l += 256) {
            int r = l >> 2, kq = l & 3;
            float4 v = *(const float4*)&A[(size_t)(bm + r) * K + k0 + kq * 4];
            As[kq * 4 + 0][r] = v.x; As[kq * 4 + 1][r] = v.y;
            As[kq * 4 + 2][r] = v.z; As[kq * 4 + 3][r] = v.w;
        }
        if (!TRANSB) {
#pragma unroll
            for (int l = tid; l < 512; l += 256) {
                int r = l >> 2, kq = l & 3;
                float4 v = *(const float4*)&B[(size_t)(bn + r) * K + k0 + kq * 4];
                Bs[kq * 4 + 0][r] = v.x; Bs[kq * 4 + 1][r] = v.y;
                Bs[kq * 4 + 2][r] = v.z; Bs[kq * 4 + 3][r] = v.w;
            }
        } else {
#pragma unroll
            for (int l = tid; l < 512; l += 256) {
                int k = l >> 5, nq = l & 31;
                *(float4*)&Bs[k][nq * 4] =
                    *(const float4*)&B[(size_t)(k0 + k) * N + bn + nq * 4];
            }
        }
        __syncthreads();

#pragma unroll
        for (int k = 0; k < BK; k++) {
            float4 av0 = *(const float4*)&As[k][m0];
            float4 av1 = *(const float4*)&As[k][m0 + 4];
            u64 bp[4];
            bp[0] = *(const u64*)&Bs[k][n0];
            bp[1] = *(const u64*)&Bs[k][n0 + 2];
            bp[2] = *(const u64*)&Bs[k][n0 + 4];
            bp[3] = *(const u64*)&Bs[k][n0 + 6];
            float am[8] = {av0.x, av0.y, av0.z, av0.w, av1.x, av1.y, av1.z, av1.w};
#pragma unroll
            for (int i = 0; i < 8; i++) {
                u64 ad = pack2(am[i], am[i]);
#pragma unroll
                for (int j = 0; j < 4; j++) fma2(acc[i][j], ad, bp[j]);
            }
        }
        __syncthreads();
    }

#pragma unroll
    for (int i = 0; i < 8; i++) {
        int m = bm + m0 + i;
        float2 p0 = unpack2(acc[i][0]), p1 = unpack2(acc[i][1]);
        float2 p2 = unpack2(acc[i][2]), p3 = unpack2(acc[i][3]);
        float4 v0 = make_float4(p0.x, p0.y, p1.x, p1.y);
        float4 v1 = make_float4(p2.x, p2.y, p3.x, p3.y);
        *(float4*)&Y[(size_t)m * N + bn + n0]     = v0;
        *(float4*)&Y[(size_t)m * N + bn + n0 + 4] = v1;
    }
}

// ------------- per-bm-group barrier (16 blocks each, all co-resident) ---------
__device__ __forceinline__ void groupbar(int gid, unsigned target)
{
    __threadfence();
    __syncthreads();
    if (threadIdx.x == 0) {
        if (atomicAdd(&g_bcnt8[gid], 1u) == 15u) {
            g_bcnt8[gid] = 0u;
            __threadfence();
            g_bgen8[gid] = target;
        } else {
            while (g_bgen8[gid] < target) { }
        }
    }
    __syncthreads();
}

// ------------- persistent LSTM layer: 512 threads, resident-B + 3-slot ring ---
// Step 0 skips the GEMM entirely (h_prev == 0 -> gates = gin exactly).
#define LSR_A_LO  16640
#define LSR_RES   33280
#define LSR_RING  (33280 + 5*10240)          // 84480
#define LSR_SMEMU (84480 + 3*10240)          // 115200 u16
#define LSR_SMEM  (LSR_SMEMU*2)              // 230400 bytes

__device__ __forceinline__ void lsr_issue_chunk(uint32_t smb, uint32_t off_u16,
                                                int bn, int k0, int tid)
{
    int r = tid >> 2, seg = (tid & 3) * 8;
    size_t g = (size_t)(bn + r) * HID + k0 + seg;
    uint32_t d = smb + (off_u16 + (uint32_t)(r * 40 + seg)) * 2;
    cp16(d, g_whqhi + g);
    cp16(d + 5120 * 2, g_whqlo + g);
}

__global__ void __launch_bounds__(512) lstm_layer_mma_kernel(int store_all)
{
    extern __shared__ u16 smu[];
    uint32_t smb = smem_u32(smu);
    int tid  = threadIdx.x;
    int w    = tid >> 5;
    int lane = tid & 31;
    int bn = blockIdx.x * 128;
    int bm = blockIdx.y * 32;
    int gid = blockIdx.y;
    int wm = (w & 1) * 16;
    int wn = (w >> 1) * 16;            // 8 n-slices of 16 gates

    int mat = lane >> 3, mi = lane & 7;
    uint32_t aoff = (uint32_t)((wm + (mat & 1) * 8 + mi) * 1040 + (mat >> 1) * 16);
    uint32_t boff = (uint32_t)((wn + (mat >> 1) * 8 + mi) * 80 + (mat & 1) * 16);

    int grp = lane >> 2, t2 = lane & 3;
    int m0r = bm + wm + grp;
    bool owner = (t2 & 1) == 0;

    float cst[2][2];
#pragma unroll
    for (int j = 0; j < 2; j++) { cst[j][0] = 0.0f; cst[j][1] = 0.0f; }

    // prologue: resident chunks 0..4 (one group), then ring chunks 5,6
    for (int c = 0; c < 5; c++)
        lsr_issue_chunk(smb, (uint32_t)(LSR_RES + c * 10240), bn, c * 32, tid);
    CP_COMMIT();
    lsr_issue_chunk(smb, (uint32_t)(LSR_RING + 0 * 10240), bn, 5 * 32, tid);
    CP_COMMIT();
    lsr_issue_chunk(smb, (uint32_t)(LSR_RING + 1 * 10240), bn, 6 * 32, tid);
    CP_COMMIT();

    for (int s = 0; s < SEQ; s++) {
        const u16* hp_hi = g_hhi + (s & 1) * BH;
        const u16* hp_lo = g_hlo + (s & 1) * BH;
        u16* hn_hi = g_hhi + ((s + 1) & 1) * BH;
        u16* hn_lo = g_hlo + ((s + 1) & 1) * BH;

        // prefetch this step's gin into registers (no h dependency)
        float2 pg0[2], pg1[2];
#pragma unroll
        for (int nj = 0; nj < 2; nj++) {
            int ncol = bn + wn + nj * 8 + t2 * 2;
            const float* gp = &g_gin[((size_t)(s * BATCH + m0r)) * G4 + ncol];
            pg0[nj] = *(const float2*)gp;
            pg1[nj] = *(const float2*)(gp + 8 * G4);
        }

        float acc[2][4];
#pragma unroll
        for (int j = 0; j < 2; j++)
#pragma unroll
            for (int q = 0; q < 4; q++) acc[j][q] = 0.0f;

        if (s > 0) {
            // group barrier: previous step's h stores must be visible
            groupbar(gid, (unsigned)s);

            // A load (h prev, 32 rows x 512 u16, hi+lo) -- 512 threads
#pragma unroll
            for (int t = 0; t < 4; t++) {
                int i = tid + t * 512;          // 0..2047
                int r = i >> 6, cseg = (i & 63) * 8;
                size_t g = (size_t)(bm + r) * HID + cseg;
                cp16(smb + (uint32_t)((r * 520 + cseg) * 2), hp_hi + g);
                cp16(smb + (uint32_t)((LSR_A_LO + r * 520 + cseg) * 2), hp_lo + g);
            }
            CP_COMMIT();

            // chunk 0 gate: A (+ anything earlier) fully arrived
            CP_WAIT0();
            __syncthreads();

            for (int ch = 0; ch < 16; ch++) {
                uint32_t bchunk;
                if (ch < 5) {
                    bchunk = (uint32_t)(LSR_RES + ch * 10240);
                } else {
                    if (ch > 5) {                 // ch==5 already covered by wait0
                        CP_WAIT1();
                        __syncthreads();
                    }
                    if (ch + 2 <= 15) {
                        int j = ch + 2;
                        lsr_issue_chunk(smb, (uint32_t)(LSR_RING + ((j - 5) % 3) * 10240),
                                        bn, j * 32, tid);
                        CP_COMMIT();
                    }
                    bchunk = (uint32_t)(LSR_RING + ((ch - 5) % 3) * 10240);
                }

                uint32_t bbase = smb + bchunk * 2 + boff;
#pragma unroll
                for (int k16 = 0; k16 < 2; k16++) {
                    uint32_t ka = (uint32_t)(ch * 64 + k16 * 32);
                    uint32_t kb = (uint32_t)(k16 * 32);
                    uint32_t ah[4], al[4], bh[4], bl[4];
                    ldm_x4(ah, smb + aoff + ka);
                    ldm_x4(al, smb + (uint32_t)(LSR_A_LO * 2) + aoff + ka);
                    ldm_x4(bh, bbase + kb);
                    ldm_x4(bl, bbase + (uint32_t)(5120 * 2) + kb);

                    mma16816(acc[0], ah, bh[0], bh[1]);
                    mma16816(acc[0], ah, bl[0], bl[1]);
                    mma16816(acc[0], al, bh[0], bh[1]);
                    mma16816(acc[1], ah, bh[2], bh[3]);
                    mma16816(acc[1], ah, bl[2], bl[3]);
                    mma16816(acc[1], al, bh[2], bh[3]);
                }
            }

            // all ring reads done before next step reuses slots 0/1
            __syncthreads();
        }

        if (s + 1 < SEQ) {
            lsr_issue_chunk(smb, (uint32_t)(LSR_RING + 0 * 10240), bn, 5 * 32, tid);
            CP_COMMIT();
            lsr_issue_chunk(smb, (uint32_t)(LSR_RING + 1 * 10240), bn, 6 * 32, tid);
            CP_COMMIT();
        }

        // epilogue: prefetched gin, gate pair-exchange, LSTM cell, h store
#pragma unroll
        for (int nj = 0; nj < 2; nj++) {
            int ncol = bn + wn + nj * 8 + t2 * 2;
            float fa = acc[nj][0] + pg0[nj].x;
            float fb = acc[nj][1] + pg0[nj].y;
            float fc = acc[nj][2] + pg1[nj].x;
            float fd = acc[nj][3] + pg1[nj].y;
            float pa = __shfl_xor_sync(0xffffffffu, fa, 1);
            float pb = __shfl_xor_sync(0xffffffffu, fb, 1);
            float pc = __shfl_xor_sync(0xffffffffu, fc, 1);
            float pd = __shfl_xor_sync(0xffffffffu, fd, 1);
            if (owner) {
                int u = ncol >> 2;
                {
                    float ig = sigmoidf_(fa), fg = sigmoidf_(fb);
                    float gg = tanhf(pa),     og = sigmoidf_(pb);
                    float cn = fg * cst[nj][0] + ig * gg;
                    cst[nj][0] = cn;
                    float hv = og * tanhf(cn);
                    u16 hi, lo; split_bf16(hv, hi, lo);
                    size_t idx = (size_t)m0r * HID + u;
                    st_cg_u16(&hn_hi[idx], hi);
                    st_cg_u16(&hn_lo[idx], lo);
                    if (store_all) {
                        size_t oidx = ((size_t)(s * BATCH + m0r)) * HID + u;
                        g_ahi[oidx] = hi; g_alo[oidx] = lo;
                    }
                }
                {
                    float ig = sigmoidf_(fc), fg = sigmoidf_(fd);
                    float gg = tanhf(pc),     og = sigmoidf_(pd);
                    float cn = fg * cst[nj][1] + ig * gg;
                    cst[nj][1] = cn;
                    float hv = og * tanhf(cn);
                    u16 hi, lo; split_bf16(hv, hi, lo);
                    size_t idx = (size_t)(m0r + 8) * HID + u;
                    st_cg_u16(&hn_hi[idx], hi);
                    st_cg_u16(&hn_lo[idx], lo);
                    if (store_all) {
                        size_t oidx = ((size_t)(s * BATCH + m0r + 8)) * HID + u;
                        g_ahi[oidx] = hi; g_alo[oidx] = lo;
                    }
                }
            }
        }
    }
}

// ------------- beff[n] = bcat[n] + sum_e Wicat[n][e] * b_proj[e] -------------
__global__ void __launch_bounds__(256) beff_kernel(const float* __restrict__ bproj)
{
    int n = blockIdx.x * 256 + threadIdx.x;
    if (n >= G4) return;
    float s = g_bcat[n];
    const float* w = &g_wicat[n * EMB];
    for (int e = 0; e < EMB; e++) s += w[e] * bproj[e];
    g_beff[n] = s;
}

// ------------- reset group barriers -------------
__global__ void reset_bar_kernel()
{
    int i = threadIdx.x;
    if (i < 8) { g_bcnt8[i] = 0u; g_bgen8[i] = 0u; }
}

// =============================== launch ===============================
extern "C" void kernel_launch(void* const* d_in, const int* in_sizes, int n_in,
                              void* d_out, int out_size)
{
    const int*   X    = (const int*)  d_in[0];
    const float* C    = (const float*)d_in[1];
    const float* Wii  = (const float*)d_in[2];
    const float* Whi  = (const float*)d_in[3];
    const float* bi   = (const float*)d_in[4];
    const float* Wif  = (const float*)d_in[5];
    const float* Whf  = (const float*)d_in[6];
    const float* bf   = (const float*)d_in[7];
    const float* Wig  = (const float*)d_in[8];
    const float* Whg  = (const float*)d_in[9];
    const float* bg   = (const float*)d_in[10];
    const float* Wio  = (const float*)d_in[11];
    const float* Who  = (const float*)d_in[12];
    const float* bo   = (const float*)d_in[13];
    const float* Wp   = (const float*)d_in[14];   // [EMB, HID]
    const float* bp   = (const float*)d_in[15];   // [EMB]
    const float* Wfin = (const float*)d_in[16];   // [N_CLASS, HID]
    const float* bfin = (const float*)d_in[17];   // [N_CLASS]
    float* out = (float*)d_out;

    float *p_gin, *p_wicat, *p_bcat, *p_weff, *p_beff;
    u16 *p_ahi, *p_alo, *p_bhi, *p_blo, *p_hhi, *p_hlo;
    u16 *p_w1hi, *p_w1lo, *p_w2hi, *p_w2lo;
    cudaGetSymbolAddress((void**)&p_gin,   g_gin);
    cudaGetSymbolAddress((void**)&p_wicat, g_wicat);
    cudaGetSymbolAddress((void**)&p_bcat,  g_bcat);
    cudaGetSymbolAddress((void**)&p_weff,  g_weff);
    cudaGetSymbolAddress((void**)&p_beff,  g_beff);
    cudaGetSymbolAddress((void**)&p_ahi,   g_ahi);
    cudaGetSymbolAddress((void**)&p_alo,   g_alo);
    cudaGetSymbolAddress((void**)&p_bhi,   g_bhi);
    cudaGetSymbolAddress((void**)&p_blo,   g_blo);
    cudaGetSymbolAddress((void**)&p_hhi,   g_hhi);
    cudaGetSymbolAddress((void**)&p_hlo,   g_hlo);
    cudaGetSymbolAddress((void**)&p_w1hi,  g_w1hi);
    cudaGetSymbolAddress((void**)&p_w1lo,  g_w1lo);
    cudaGetSymbolAddress((void**)&p_w2hi,  g_w2hi);
    cudaGetSymbolAddress((void**)&p_w2lo,  g_w2lo);

    cudaFuncSetAttribute(mma_gemm_kernel,
                         cudaFuncAttributeMaxDynamicSharedMemorySize, MG_SMEM);
    cudaFuncSetAttribute(lstm_layer_mma_kernel,
                         cudaFuncAttributeMaxDynamicSharedMemorySize, LSR_SMEM);

    // 1) weight prep (whq split, wicat fp32 + split)
    prep_concat_kernel<<<(G4 * HID) / 256, 256>>>(Wii, Whi, bi, Wif, Whf, bf,
                                                  Wig, Whg, bg, Wio, Who, bo);
    // 2) embedding gather -> split bf16 A
    embed_kernel<<<MB_, EMB>>>(X, C);

    // 3) Gin0 = Emb @ Wicat^T + bcat   [16384 x 2048], K=256
    mma_gemm_kernel<<<dim3(G4 / 128, MB_ / 128), 256, MG_SMEM>>>(
        p_ahi, p_alo, p_w1hi, p_w1lo, p_bcat, p_gin, G4, EMB);

    // 4) fold projection: Weff = Wicat @ Wp (fp32), beff; cvt to split bf16
    gemm128_kernel<true><<<dim3(HID / 128, G4 / 128), 256>>>(
        p_wicat, Wp, nullptr, p_weff, G4, HID, EMB);
    beff_kernel<<<G4 / 256, 256>>>(bp);
    cvt_split4_kernel<<<(G4 * HID / 4) / 256, 256>>>(p_weff, p_w2hi, p_w2lo,
                                                     G4 * HID / 4);

    // 5) layer-0 recurrence (persistent; s=0 GEMM skipped; h0all -> g_ahi/alo)
    reset_bar_kernel<<<1, 32>>>();
    lstm_layer_mma_kernel<<<dim3(16, 8), 512, LSR_SMEM>>>(1);

    // 6) Gin1 = H0all @ Weff^T + beff  [16384 x 2048], K=512
    mma_gemm_kernel<<<dim3(G4 / 128, MB_ / 128), 256, MG_SMEM>>>(
        p_ahi, p_alo, p_w2hi, p_w2lo, p_beff, p_gin, G4, HID);

    // 7) layer-1 recurrence
    reset_bar_kernel<<<1, 32>>>();
    lstm_layer_mma_kernel<<<dim3(16, 8), 512, LSR_SMEM>>>(0);

    // 8) logits = h_last @ Wfin^T + bfin  [256 x 32000], K=512
    //    (SEQ even -> final h in buffer 0 of g_hhi/g_hlo)
    cvt_split4_kernel<<<(N_CLASS * HID / 4) / 256, 256>>>(Wfin, p_bhi, p_blo,
                                                          N_CLASS * HID / 4);
    mma_gemm_kernel<<<dim3(N_CLASS / 128, BATCH / 128), 256, MG_SMEM>>>(
        p_hhi, p_hlo, p_bhi, p_blo, bfin, out, N_CLASS, HID);
}